// round 13
// baseline (speedup 1.0000x reference)
#include <cuda_runtime.h>
#include <cuda_fp16.h>
#include <math.h>
#include <cstdint>

// ---------------------------------------------------------------------------
// Problem constants (PerceiverResampler)
// ---------------------------------------------------------------------------
#define DIMV   1024
#define NDEPTH 6
#define NHEADS 16
#define DHEAD  64
#define INNERV 1024
#define NLAT   64
#define FFV    4096
#define BTV    32
#define MEDIA  1024
#define LNEPS  1e-5f

// ---------------------------------------------------------------------------
// Scratch (static device allocations)
// ---------------------------------------------------------------------------
__device__ __half g_xhat[(size_t)BTV * MEDIA * DIMV];
__device__ __half g_kvm [NDEPTH][(size_t)BTV * MEDIA * 2 * INNERV];   // per-layer KV
__device__ float  g_lat [(size_t)BTV * NLAT * DIMV];
__device__ __half g_latn[(size_t)BTV * NLAT * DIMV];
__device__ __half g_qkv [(size_t)BTV * NLAT * 3 * INNERV];    // fused q | k | v (half)
__device__ __half g_attn[(size_t)BTV * NLAT * INNERV];
__device__ __half g_ffh [(size_t)BTV * NLAT * FFV];
// k-pair-packed half weights: u32[k/2][n] = {w[k][n], w[k+1][n]}
__device__ uint32_t g_wkvP [(size_t)NDEPTH * (DIMV/2) * 2 * INNERV];   // scaled by nm_g
__device__ uint32_t g_wqkvP[(size_t)NDEPTH * (DIMV/2) * 3 * INNERV];   // wq | wkv plain
__device__ uint32_t g_woP  [(size_t)NDEPTH * (INNERV/2) * DIMV];
__device__ uint32_t g_w1P  [(size_t)NDEPTH * (DIMV/2) * FFV];
__device__ uint32_t g_w2P  [(size_t)NDEPTH * (FFV/2) * DIMV];
__device__ float g_kvbias[(size_t)NDEPTH * 2 * INNERV];                // nm_b @ wkv

// ---------------------------------------------------------------------------
// helpers
// ---------------------------------------------------------------------------
__device__ __forceinline__ uint32_t smem_u32(const void* p) {
    uint32_t a;
    asm("{ .reg .u64 t; cvta.to.shared.u64 t, %1; cvt.u32.u64 %0, t; }"
        : "=r"(a) : "l"(p));
    return a;
}
__device__ __forceinline__ void cp_async16(uint32_t dst, const void* src) {
    asm volatile("cp.async.cg.shared.global [%0], [%1], 16;" :: "r"(dst), "l"(src));
}
__device__ __forceinline__ void cp_commit() {
    asm volatile("cp.async.commit_group;" ::: "memory");
}
__device__ __forceinline__ void cp_wait1() {
    asm volatile("cp.async.wait_group 1;" ::: "memory");
}
__device__ __forceinline__ void cp_wait0() {
    asm volatile("cp.async.wait_group 0;" ::: "memory");
}
__device__ __forceinline__ void mma_f16(float& c0, float& c1, float& c2, float& c3,
                                        uint32_t a0, uint32_t a1, uint32_t a2, uint32_t a3,
                                        uint32_t b0, uint32_t b1) {
    asm volatile(
        "mma.sync.aligned.m16n8k16.row.col.f32.f16.f16.f32 "
        "{%0,%1,%2,%3}, {%4,%5,%6,%7}, {%8,%9}, {%0,%1,%2,%3};"
        : "+f"(c0), "+f"(c1), "+f"(c2), "+f"(c3)
        : "r"(a0), "r"(a1), "r"(a2), "r"(a3), "r"(b0), "r"(b1));
}
__device__ __forceinline__ void ldsm4(uint32_t* r, uint32_t addr) {
    asm volatile("ldmatrix.sync.aligned.m8n8.x4.shared.b16 {%0,%1,%2,%3}, [%4];"
                 : "=r"(r[0]), "=r"(r[1]), "=r"(r[2]), "=r"(r[3]) : "r"(addr));
}
__device__ __forceinline__ void ldsm4t(uint32_t* r, uint32_t addr) {
    asm volatile("ldmatrix.sync.aligned.m8n8.x4.trans.shared.b16 {%0,%1,%2,%3}, [%4];"
                 : "=r"(r[0]), "=r"(r[1]), "=r"(r[2]), "=r"(r[3]) : "r"(addr));
}
__device__ __forceinline__ float gelu_exact(float x) {
    return 0.5f * x * (1.0f + erff(x * 0.70710678118654752f));
}

// ---------------------------------------------------------------------------
// Weight pack with output stride/offset
// ---------------------------------------------------------------------------
__global__ void __launch_bounds__(256) wpack_kernel(
    const float* __restrict__ in, uint32_t* __restrict__ out,
    int K2N, int N, int K, const float* __restrict__ scale,
    int ldo, int coloff)
{
    int idx = blockIdx.x * 256 + threadIdx.x;
    int layer = idx / K2N;
    int rem   = idx - layer * K2N;
    int k2 = rem / N;
    int n  = rem - k2 * N;
    const float* base = in + ((size_t)layer * K + 2 * k2) * N + n;
    float v0 = base[0], v1 = base[N];
    if (scale) {
        v0 *= scale[layer * K + 2 * k2];
        v1 *= scale[layer * K + 2 * k2 + 1];
    }
    __half2 h = __floats2half2_rn(v0, v1);
    out[((size_t)layer * (K / 2) + k2) * ldo + coloff + n] = *(uint32_t*)&h;
}

// ---------------------------------------------------------------------------
// bias[layer][n] = sum_k b[layer][k] * W[layer][k][n]  (fp32)
// ---------------------------------------------------------------------------
__global__ void __launch_bounds__(256) bias_kernel(
    const float* __restrict__ b, const float* __restrict__ W,
    float* __restrict__ out, int K, int N)
{
    int layer = blockIdx.y;
    int n = blockIdx.x * 256 + threadIdx.x;
    const float* Wl = W + (size_t)layer * K * N;
    const float* bl = b + (size_t)layer * K;
    float s = 0.f;
    for (int k = 0; k < K; k++) s = fmaf(bl[k], Wl[(size_t)k * N + n], s);
    out[(size_t)layer * N + n] = s;
}

// ---------------------------------------------------------------------------
// lat broadcast
// ---------------------------------------------------------------------------
__global__ void __launch_bounds__(256) init_lat_kernel(
    const float* __restrict__ latents, float* __restrict__ lat)
{
    int idx4 = blockIdx.x * 256 + threadIdx.x;
    int row  = idx4 >> 8;
    int c4   = idx4 & 255;
    int n    = row & 63;
    float4 v = *(const float4*)(latents + (size_t)n * DIMV + (c4 << 2));
    *(float4*)(lat + ((size_t)row << 10) + (c4 << 2)) = v;
}

// ---------------------------------------------------------------------------
// LayerNorm rows of 1024.  outHalf: write __half else float.
// ---------------------------------------------------------------------------
__global__ void __launch_bounds__(256) ln_kernel(
    const float* __restrict__ in, void* __restrict__ out,
    const float* __restrict__ g, const float* __restrict__ b, int outHalf)
{
    __shared__ float red[2][8];
    size_t row = blockIdx.x;
    const float* x = in + row * DIMV;
    int t = threadIdx.x;

    float4 v = *(const float4*)(x + (t << 2));
    float s  = v.x + v.y + v.z + v.w;
    float ss = v.x*v.x + v.y*v.y + v.z*v.z + v.w*v.w;
    #pragma unroll
    for (int off = 16; off; off >>= 1) {
        s  += __shfl_xor_sync(0xffffffffu, s,  off);
        ss += __shfl_xor_sync(0xffffffffu, ss, off);
    }
    int w = t >> 5, lane = t & 31;
    if (lane == 0) { red[0][w] = s; red[1][w] = ss; }
    __syncthreads();
    if (t == 0) {
        float ts = 0.f, tss = 0.f;
        #pragma unroll
        for (int i = 0; i < 8; i++) { ts += red[0][i]; tss += red[1][i]; }
        red[0][0] = ts; red[1][0] = tss;
    }
    __syncthreads();
    float mean = red[0][0] * (1.f / 1024.f);
    float var  = red[1][0] * (1.f / 1024.f) - mean * mean;
    float inv  = rsqrtf(var + LNEPS);

    float gx = 1.f, gy = 1.f, gz = 1.f, gw = 1.f;
    float bx = 0.f, by = 0.f, bz = 0.f, bw = 0.f;
    if (g) {
        float4 gg = *(const float4*)(g + (t << 2));
        float4 bb = *(const float4*)(b + (t << 2));
        gx = gg.x; gy = gg.y; gz = gg.z; gw = gg.w;
        bx = bb.x; by = bb.y; bz = bb.z; bw = bb.w;
    }
    float4 o;
    o.x = (v.x - mean) * inv * gx + bx;
    o.y = (v.y - mean) * inv * gy + by;
    o.z = (v.z - mean) * inv * gz + bz;
    o.w = (v.w - mean) * inv * gw + bw;
    if (outHalf) {
        __half2* oh = (__half2*)((__half*)out + row * DIMV + (t << 2));
        oh[0] = __floats2half2_rn(o.x, o.y);
        oh[1] = __floats2half2_rn(o.z, o.w);
    } else {
        *(float4*)((float*)out + row * DIMV + (t << 2)) = o;
    }
}

// ---------------------------------------------------------------------------
// fp16 mma.sync GEMM, 3-stage cp.async pipeline, hoisted/rotated smem bases.
//   <4,4>: kvm config, BK=64.  <2,2>: latent config, BK=32.
//   flags: 1 = gelu, 2 = half output.
// ---------------------------------------------------------------------------
#define SB 136    // B smem row stride in u32
template <int IM, int CH>
__global__ void __launch_bounds__(256, (IM == 4) ? 2 : 3) gemm_h(
    const __half* __restrict__ A, const uint32_t* __restrict__ Bp, void* __restrict__ Cv,
    int K, int lda, int ldbn, int ldc,
    const float* __restrict__ bias, const float* __restrict__ resid, int flags)
{
    constexpr int BM  = 32 * IM;
    constexpr int SAv = 16 * CH + 8;   // A smem row stride in halves
    constexpr int BR  = 8 * CH;        // B k2-rows per stage
    extern __shared__ char smraw[];
    __half*   As = (__half*)smraw;                               // [3][BM][SAv]
    uint32_t* Bs = (uint32_t*)(smraw + 3 * BM * SAv * 2);        // [3][BR][SB]

    const int tid  = threadIdx.x;
    const int wid  = tid >> 5;
    const int lane = tid & 31;
    const int wm   = wid >> 2;
    const int wn   = wid & 3;
    const int g    = lane >> 2;
    const int t    = lane & 3;
    const int m0   = blockIdx.y * BM;
    const int n0   = blockIdx.x * 128;
    const int NK   = K / (16 * CH);
    const int wbase = wm * (IM * 16);
    const int lrow = (lane & 7) + ((lane >> 3) & 1) * 8;
    const int lcol = (lane >> 4) * 8;

    const uint32_t aBase = smem_u32(As);
    const uint32_t bBase = smem_u32(Bs);

    // hoisted per-buffer fragment base addresses (rotate each k-tile)
    uint32_t aP0 = aBase + ((uint32_t)(0 * BM + wbase + lrow) * SAv + lcol) * 2;
    uint32_t aP1 = aBase + ((uint32_t)(1 * BM + wbase + lrow) * SAv + lcol) * 2;
    uint32_t aP2 = aBase + ((uint32_t)(2 * BM + wbase + lrow) * SAv + lcol) * 2;
    const uint32_t* bQ0 = Bs + (size_t)(0 * BR + t) * SB + wn * 32 + g;
    const uint32_t* bQ1 = Bs + (size_t)(1 * BR + t) * SB + wn * 32 + g;
    const uint32_t* bQ2 = Bs + (size_t)(2 * BR + t) * SB + wn * 32 + g;

    float acc[IM][4][4];
    #pragma unroll
    for (int i = 0; i < IM; i++)
        #pragma unroll
        for (int j = 0; j < 4; j++)
            #pragma unroll
            for (int r = 0; r < 4; r++) acc[i][j][r] = 0.f;

    auto load_tile = [&](int kt, int buf) {
        const int kg = kt * 16 * CH;
        #pragma unroll
        for (int p = 0; p < BM * CH / 128; p++) {
            int idx = p * 256 + tid;
            int row = idx / (2 * CH);
            int c   = (idx % (2 * CH)) << 3;
            cp_async16(aBase + ((buf * BM + row) * SAv + c) * 2,
                       A + (size_t)(m0 + row) * lda + kg + c);
        }
        #pragma unroll
        for (int p = 0; p < CH; p++) {
            int idx = p * 256 + tid;
            int r   = idx >> 5;
            int c4  = (idx & 31) << 2;
            cp_async16(bBase + ((buf * BR + r) * SB + c4) * 4,
                       Bp + (size_t)((kg >> 1) + r) * ldbn + n0 + c4);
        }
    };

    load_tile(0, 0);
    cp_commit();
    if (1 < NK) { load_tile(1, 1); }
    cp_commit();

    for (int kt = 0; kt < NK; kt++) {
        if (kt + 1 < NK) cp_wait1(); else cp_wait0();
        __syncthreads();
        if (kt + 2 < NK) { load_tile(kt + 2, (kt + 2) % 3); }
        cp_commit();

        // current buffer bases are aP0 / bQ0 (rotated below)
        #pragma unroll
        for (int c = 0; c < CH; c++) {
            uint32_t af[IM][4], bf[4][2];
            #pragma unroll
            for (int i = 0; i < IM; i++)
                ldsm4(af[i], aP0 + ((uint32_t)(i * 16) * SAv + c * 16) * 2);
            #pragma unroll
            for (int j = 0; j < 4; j++) {
                bf[j][0] = bQ0[(size_t)(c * 8)     * SB + j * 8];
                bf[j][1] = bQ0[(size_t)(c * 8 + 4) * SB + j * 8];
            }
            #pragma unroll
            for (int i = 0; i < IM; i++)
                #pragma unroll
                for (int j = 0; j < 4; j++)
                    mma_f16(acc[i][j][0], acc[i][j][1], acc[i][j][2], acc[i][j][3],
                            af[i][0], af[i][1], af[i][2], af[i][3],
                            bf[j][0], bf[j][1]);
        }
        // rotate buffers: next iteration's current = old aP1/bQ1
        uint32_t at = aP0; aP0 = aP1; aP1 = aP2; aP2 = at;
        const uint32_t* bt_ = bQ0; bQ0 = bQ1; bQ1 = bQ2; bQ2 = bt_;
    }

    const int doGelu  = flags & 1;
    const int outHalf = flags & 2;
    #pragma unroll
    for (int i = 0; i < IM; i++) {
        int mrow = m0 + wbase + i * 16 + g;
        #pragma unroll
        for (int j = 0; j < 4; j++) {
            int ncol = n0 + wn * 32 + j * 8 + 2 * t;
            #pragma unroll
            for (int half = 0; half < 2; half++) {
                int mr = mrow + half * 8;
                float c0 = acc[i][j][2 * half + 0];
                float c1 = acc[i][j][2 * half + 1];
                if (bias) {
                    float2 bv = *(const float2*)(bias + ncol);
                    c0 += bv.x; c1 += bv.y;
                }
                if (resid) {
                    float2 rv = *(const float2*)(resid + (size_t)mr * ldc + ncol);
                    c0 += rv.x; c1 += rv.y;
                }
                if (doGelu) { c0 = gelu_exact(c0); c1 = gelu_exact(c1); }
                if (outHalf) {
                    *(__half2*)((__half*)Cv + (size_t)mr * ldc + ncol) =
                        __floats2half2_rn(c0, c1);
                } else {
                    float2 o; o.x = c0; o.y = c1;
                    *(float2*)((float*)Cv + (size_t)mr * ldc + ncol) = o;
                }
            }
        }
    }
}

// ---------------------------------------------------------------------------
// fp16 tensor-core attention (unchanged from R11).
// ---------------------------------------------------------------------------
__global__ void __launch_bounds__(128, 4) attn_h_kernel(
    const __half* __restrict__ qkv, const __half* __restrict__ kvm,
    __half* __restrict__ outp)
{
    __shared__ __half ks[2][64][72];
    __shared__ __half vs[2][64][72];
    __shared__ __half ps[4][16][72];

    const int bt   = blockIdx.x >> 4;
    const int h    = blockIdx.x & 15;
    const int tid  = threadIdx.x;
    const int w    = tid >> 5;
    const int lane = tid & 31;
    const int g    = lane >> 2;
    const int t    = lane & 3;
    const int lrow = (lane & 7) + ((lane >> 3) & 1) * 8;
    const int lcol = (lane >> 4) * 8;

    uint32_t qa[4][4];
    {
        const __half* Qb = qkv + ((size_t)bt * 64 + w * 16) * 3072 + h * DHEAD;
        const __half2 sc = __float2half2_rn(0.125f);
        #pragma unroll
        for (int c = 0; c < 4; c++) {
            __half2 v0 = __hmul2(*(const __half2*)(Qb + (size_t)g       * 3072 + 16 * c + 2 * t),     sc);
            __half2 v1 = __hmul2(*(const __half2*)(Qb + (size_t)(g + 8) * 3072 + 16 * c + 2 * t),     sc);
            __half2 v2 = __hmul2(*(const __half2*)(Qb + (size_t)g       * 3072 + 16 * c + 2 * t + 8), sc);
            __half2 v3 = __hmul2(*(const __half2*)(Qb + (size_t)(g + 8) * 3072 + 16 * c + 2 * t + 8), sc);
            qa[c][0] = *(uint32_t*)&v0;
            qa[c][1] = *(uint32_t*)&v1;
            qa[c][2] = *(uint32_t*)&v2;
            qa[c][3] = *(uint32_t*)&v3;
        }
    }

    float out[8][4];
    #pragma unroll
    for (int j = 0; j < 8; j++)
        #pragma unroll
        for (int r = 0; r < 4; r++) out[j][r] = 0.f;
    float m0 = -1e30f, m1 = -1e30f, l0 = 0.f, l1 = 0.f;

    const uint32_t kb0 = smem_u32(&ks[0][0][0]);
    const uint32_t vb0 = smem_u32(&vs[0][0][0]);

    auto load_chunk = [&](int ch, int buf) {
        const __half* base;
        size_t rs;
        if (ch < 16) { base = kvm + ((size_t)bt * 1024 + ch * 64) * 2048 + h * DHEAD; rs = 2048; }
        else         { base = qkv + ((size_t)bt * 64) * 3072 + 1024 + h * DHEAD;      rs = 3072; }
        #pragma unroll
        for (int p = 0; p < 4; p++) {
            int idx = p * 128 + tid;
            int r   = idx >> 3;
            int c8  = (idx & 7) << 3;
            cp_async16(kb0 + ((buf * 64 + r) * 72 + c8) * 2,
                       base + (size_t)r * rs + c8);
            cp_async16(vb0 + ((buf * 64 + r) * 72 + c8) * 2,
                       base + (size_t)r * rs + 1024 + c8);
        }
    };

    load_chunk(0, 0);
    cp_commit();

    for (int ch = 0; ch < 17; ch++) {
        const int buf = ch & 1;
        if (ch + 1 < 17) {
            load_chunk(ch + 1, buf ^ 1);
            cp_commit();
            cp_wait1();
        } else {
            cp_wait0();
        }
        __syncthreads();

        float sim[8][4];
        #pragma unroll
        for (int j = 0; j < 8; j++)
            #pragma unroll
            for (int r = 0; r < 4; r++) sim[j][r] = 0.f;
        #pragma unroll
        for (int c = 0; c < 4; c++) {
            #pragma unroll
            for (int j = 0; j < 8; j++) {
                uint32_t b0 = *(const uint32_t*)&ks[buf][8 * j + g][16 * c + 2 * t];
                uint32_t b1 = *(const uint32_t*)&ks[buf][8 * j + g][16 * c + 2 * t + 8];
                mma_f16(sim[j][0], sim[j][1], sim[j][2], sim[j][3],
                        qa[c][0], qa[c][1], qa[c][2], qa[c][3], b0, b1);
            }
        }

        float cm0 = -1e30f, cm1 = -1e30f;
        #pragma unroll
        for (int j = 0; j < 8; j++) {
            cm0 = fmaxf(cm0, fmaxf(sim[j][0], sim[j][1]));
            cm1 = fmaxf(cm1, fmaxf(sim[j][2], sim[j][3]));
        }
        cm0 = fmaxf(cm0, __shfl_xor_sync(0xffffffffu, cm0, 1));
        cm0 = fmaxf(cm0, __shfl_xor_sync(0xffffffffu, cm0, 2));
        cm1 = fmaxf(cm1, __shfl_xor_sync(0xffffffffu, cm1, 1));
        cm1 = fmaxf(cm1, __shfl_xor_sync(0xffffffffu, cm1, 2));
        float mt0 = fmaxf(m0, cm0), mt1 = fmaxf(m1, cm1);
        float corr0 = __expf(m0 - mt0), corr1 = __expf(m1 - mt1);
        float rs0 = 0.f, rs1 = 0.f;
        #pragma unroll
        for (int j = 0; j < 8; j++) {
            sim[j][0] = __expf(sim[j][0] - mt0);
            sim[j][1] = __expf(sim[j][1] - mt0);
            sim[j][2] = __expf(sim[j][2] - mt1);
            sim[j][3] = __expf(sim[j][3] - mt1);
            rs0 += sim[j][0] + sim[j][1];
            rs1 += sim[j][2] + sim[j][3];
        }
        rs0 += __shfl_xor_sync(0xffffffffu, rs0, 1);
        rs0 += __shfl_xor_sync(0xffffffffu, rs0, 2);
        rs1 += __shfl_xor_sync(0xffffffffu, rs1, 1);
        rs1 += __shfl_xor_sync(0xffffffffu, rs1, 2);
        l0 = l0 * corr0 + rs0;  m0 = mt0;
        l1 = l1 * corr1 + rs1;  m1 = mt1;
        #pragma unroll
        for (int j = 0; j < 8; j++) {
            out[j][0] *= corr0; out[j][1] *= corr0;
            out[j][2] *= corr1; out[j][3] *= corr1;
        }

        #pragma unroll
        for (int j = 0; j < 8; j++) {
            __half2 p0 = __floats2half2_rn(sim[j][0], sim[j][1]);
            __half2 p1 = __floats2half2_rn(sim[j][2], sim[j][3]);
            *(uint32_t*)&ps[w][g][8 * j + 2 * t]     = *(uint32_t*)&p0;
            *(uint32_t*)&ps[w][g + 8][8 * j + 2 * t] = *(uint32_t*)&p1;
        }
        __syncwarp();

        #pragma unroll
        for (int c = 0; c < 4; c++) {
            uint32_t af[4];
            ldsm4(af, smem_u32(&ps[w][lrow][16 * c + lcol]));
            #pragma unroll
            for (int jn = 0; jn < 4; jn++) {
                uint32_t bv[4];
                ldsm4t(bv, smem_u32(&vs[buf][16 * c + (lane & 15)][16 * jn + lcol]));
                mma_f16(out[2 * jn][0], out[2 * jn][1], out[2 * jn][2], out[2 * jn][3],
                        af[0], af[1], af[2], af[3], bv[0], bv[1]);
                mma_f16(out[2 * jn + 1][0], out[2 * jn + 1][1], out[2 * jn + 1][2], out[2 * jn + 1][3],
                        af[0], af[1], af[2], af[3], bv[2], bv[3]);
            }
        }
        __syncthreads();
    }

    float inv0 = 1.f / l0, inv1 = 1.f / l1;
    __half* O0 = outp + ((size_t)bt * 64 + w * 16 + g)     * INNERV + h * DHEAD;
    __half* O1 = outp + ((size_t)bt * 64 + w * 16 + g + 8) * INNERV + h * DHEAD;
    #pragma unroll
    for (int j = 0; j < 8; j++) {
        *(__half2*)(O0 + 8 * j + 2 * t) = __floats2half2_rn(out[j][0] * inv0, out[j][1] * inv0);
        *(__half2*)(O1 + 8 * j + 2 * t) = __floats2half2_rn(out[j][2] * inv1, out[j][3] * inv1);
    }
}

// ---------------------------------------------------------------------------
// Host orchestration: two streams, six kvm buffers (no backpressure).
//   s1: all six kvm GEMMs back-to-back after evPre.
//   stream 0: preproc + latent chain; attn_i waits evKvm[i] only.
// All waits reference events already recorded in host enqueue order.
// ---------------------------------------------------------------------------
extern "C" void kernel_launch(void* const* d_in, const int* in_sizes, int n_in,
                              void* d_out, int out_size)
{
    const float* x       = (const float*)d_in[0];
    const float* latents = (const float*)d_in[1];
    const float* nm_g    = (const float*)d_in[2];
    const float* nm_b    = (const float*)d_in[3];
    const float* nl_g    = (const float*)d_in[4];
    const float* nl_b    = (const float*)d_in[5];
    const float* wq      = (const float*)d_in[6];
    const float* wkv     = (const float*)d_in[7];
    const float* wo      = (const float*)d_in[8];
    const float* ff_g    = (const float*)d_in[9];
    const float* ff_b    = (const float*)d_in[10];
    const float* w1      = (const float*)d_in[11];
    const float* w2      = (const float*)d_in[12];
    const float* fin_g   = (const float*)d_in[13];
    const float* fin_b   = (const float*)d_in[14];

    __half *xhat, *latn, *attnH, *ffh, *qkv, *kvmAll;
    float *lat, *kvbias;
    uint32_t *wkvP, *wqkvP, *woP, *w1P, *w2P;
    cudaGetSymbolAddress((void**)&xhat,   g_xhat);
    cudaGetSymbolAddress((void**)&kvmAll, g_kvm);
    cudaGetSymbolAddress((void**)&lat,    g_lat);
    cudaGetSymbolAddress((void**)&latn,   g_latn);
    cudaGetSymbolAddress((void**)&qkv,    g_qkv);
    cudaGetSymbolAddress((void**)&attnH,  g_attn);
    cudaGetSymbolAddress((void**)&ffh,    g_ffh);
    cudaGetSymbolAddress((void**)&wkvP,   g_wkvP);
    cudaGetSymbolAddress((void**)&wqkvP,  g_wqkvP);
    cudaGetSymbolAddress((void**)&woP,    g_woP);
    cudaGetSymbolAddress((void**)&w1P,    g_w1P);
    cudaGetSymbolAddress((void**)&w2P,    g_w2P);
    cudaGetSymbolAddress((void**)&kvbias, g_kvbias);

    const size_t KVM_STRIDE = (size_t)BTV * MEDIA * 2 * INNERV;

    const int K2N_KV = (DIMV / 2) * 2 * INNERV;
    const int K2N_SQ = (DIMV / 2) * INNERV;
    const int K2N_W1 = (DIMV / 2) * FFV;
    const int K2N_W2 = (FFV / 2) * DIMV;

    const int SM44 = 3 * 128 * 72 * 2 + 3 * 32 * SB * 4;
    const int SM22 = 3 *  64 * 40 * 2 + 3 * 16 * SB * 4;
    cudaFuncSetAttribute(gemm_h<4,4>, cudaFuncAttributeMaxDynamicSharedMemorySize, SM44);
    cudaFuncSetAttribute(gemm_h<2,2>, cudaFuncAttributeMaxDynamicSharedMemorySize, SM22);

    cudaStream_t s1;
    cudaStreamCreateWithFlags(&s1, cudaStreamNonBlocking);
    cudaEvent_t evPre, evKvm[NDEPTH];
    cudaEventCreateWithFlags(&evPre, cudaEventDisableTiming);
    for (int i = 0; i < NDEPTH; i++)
        cudaEventCreateWithFlags(&evKvm[i], cudaEventDisableTiming);

    // ---- stream 0: minimal preproc needed by kvm ----
    wpack_kernel<<<NDEPTH * K2N_KV / 256, 256>>>(
        wkv, wkvP, K2N_KV, 2 * INNERV, DIMV, nm_g, 2 * INNERV, 0);
    ln_kernel<<<BTV * MEDIA, 256>>>(x, xhat, nullptr, nullptr, 1);
    bias_kernel<<<dim3(2 * INNERV / 256, NDEPTH), 256>>>(nm_b, wkv, kvbias, DIMV, 2 * INNERV);
    cudaEventRecord(evPre, 0);

    // ---- s1: ALL six kvm GEMMs back-to-back (dedicated buffers) ----
    cudaStreamWaitEvent(s1, evPre, 0);
    for (int i = 0; i < NDEPTH; i++) {
        gemm_h<4,4><<<dim3(16, 256), 256, SM44, s1>>>(
            xhat, wkvP + (size_t)i * K2N_KV, kvmAll + (size_t)i * KVM_STRIDE,
            DIMV, DIMV, 2 * INNERV, 2 * INNERV,
            kvbias + (size_t)i * 2 * INNERV, nullptr, 2);
        cudaEventRecord(evKvm[i], s1);
    }

    // ---- stream 0: rest of preproc ----
    init_lat_kernel<<<2048, 256>>>(latents, lat);
    wpack_kernel<<<NDEPTH * K2N_SQ / 256, 256>>>(
        wq, wqkvP, K2N_SQ, INNERV, DIMV, nullptr, 3 * INNERV, 0);
    wpack_kernel<<<NDEPTH * K2N_KV / 256, 256>>>(
        wkv, wqkvP, K2N_KV, 2 * INNERV, DIMV, nullptr, 3 * INNERV, INNERV);
    wpack_kernel<<<NDEPTH * K2N_SQ / 256, 256>>>(
        wo, woP, K2N_SQ, DIMV, INNERV, nullptr, DIMV, 0);
    wpack_kernel<<<NDEPTH * K2N_W1 / 256, 256>>>(
        w1, w1P, K2N_W1, FFV, DIMV, nullptr, FFV, 0);
    wpack_kernel<<<NDEPTH * K2N_W2 / 256, 256>>>(
        w2, w2P, K2N_W2, DIMV, FFV, nullptr, DIMV, 0);

    // ---- stream 0: latent chain ----
    for (int i = 0; i < NDEPTH; i++) {
        const uint32_t* wqkvP_i = wqkvP + (size_t)i * (DIMV / 2) * 3 * INNERV;
        const uint32_t* woP_i   = woP   + (size_t)i * K2N_SQ;
        const uint32_t* w1P_i   = w1P   + (size_t)i * K2N_W1;
        const uint32_t* w2P_i   = w2P   + (size_t)i * K2N_W2;

        ln_kernel<<<BTV * NLAT, 256>>>(lat, latn,
            nl_g + (size_t)i * DIMV, nl_b + (size_t)i * DIMV, 1);
        gemm_h<2,2><<<dim3(24, 32), 256, SM22>>>(latn, wqkvP_i, qkv,
            DIMV, DIMV, 3 * INNERV, 3 * INNERV, nullptr, nullptr, 2);

        cudaStreamWaitEvent(0, evKvm[i], 0);
        attn_h_kernel<<<BTV * NHEADS, 128>>>(qkv, kvmAll + (size_t)i * KVM_STRIDE, attnH);

        gemm_h<2,2><<<dim3(8, 32), 256, SM22>>>(attnH, woP_i, lat,
            INNERV, INNERV, DIMV, DIMV, nullptr, lat, 0);

        ln_kernel<<<BTV * NLAT, 256>>>(lat, latn,
            ff_g + (size_t)i * DIMV, ff_b + (size_t)i * DIMV, 1);
        gemm_h<2,2><<<dim3(32, 32), 256, SM22>>>(latn, w1P_i, ffh,
            DIMV, DIMV, FFV, FFV, nullptr, nullptr, 1 | 2);
        gemm_h<2,2><<<dim3(8, 32), 256, SM22>>>(ffh, w2P_i, lat,
            FFV, FFV, DIMV, DIMV, nullptr, lat, 0);
    }

    ln_kernel<<<BTV * NLAT, 256>>>(lat, (float*)d_out, fin_g, fin_b, 0);

    cudaEventDestroy(evPre);
    for (int i = 0; i < NDEPTH; i++) cudaEventDestroy(evKvm[i]);
    cudaStreamDestroy(s1);
}